// round 1
// baseline (speedup 1.0000x reference)
#include <cuda_runtime.h>
#include <cstdint>

#define DIM      4096
#define NPAIRS   2048
#define GRD      64
#define P_TILE   8
#define THREADS  1024
#define GRID_ELEMS (GRD * GRD)               // 4096 floats per pair
#define SMEM_BYTES (P_TILE * GRID_ELEMS * 4) // 128 KB

__global__ void __launch_bounds__(THREADS, 1)
pair_bilinear_kernel(const float* __restrict__ x,
                     const float* __restrict__ pairW,
                     const float* __restrict__ Y,
                     float* __restrict__ out,
                     int batch, int b_tile)
{
    extern __shared__ float sY[];  // P_TILE * 64 * 64 floats = 128 KB

    const int p0 = blockIdx.x * P_TILE;

    // Stage P_TILE grids of Y into shared memory (bulk, coalesced float4)
    {
        const float4* __restrict__ Yg = reinterpret_cast<const float4*>(Y + (size_t)p0 * GRID_ELEMS);
        float4* sY4 = reinterpret_cast<float4*>(sY);
        const int n4 = P_TILE * GRID_ELEMS / 4;  // 8192 float4
        #pragma unroll
        for (int i = threadIdx.x; i < n4; i += THREADS)
            sY4[i] = Yg[i];
    }
    __syncthreads();

    const int pl = threadIdx.x & (P_TILE - 1);   // pair within tile
    const int bs = threadIdx.x >> 3;             // batch sub-index (0..127)
    const int p  = p0 + pl;

    // Per-pair 2x2 weights live in registers for the whole loop
    const float4 w = *reinterpret_cast<const float4*>(pairW + (size_t)p * 4);
    // w.x = W[0][0], w.y = W[0][1], w.z = W[1][0], w.w = W[1][1]

    const float* __restrict__ sYp = sY + pl * GRID_ELEMS;

    const int bstart = blockIdx.y * b_tile;
    const int bend   = min(bstart + b_tile, batch);
    const int bstep  = THREADS / P_TILE;         // 128

    #pragma unroll 4
    for (int b = bstart + bs; b < bend; b += bstep) {
        const float2 xv = *reinterpret_cast<const float2*>(x + (size_t)b * DIM + 2 * p);
        const float x0 = xv.x, x1 = xv.y;

        // xp[j] = x0 * W[0][j] + x1 * W[1][j]
        const float xp0 = fmaf(x0, w.x, x1 * w.z);
        const float xp1 = fmaf(x0, w.y, x1 * w.w);

        float g0 = fminf(fmaxf(xp0 * 63.0f, 0.0f), 63.0f);
        float g1 = fminf(fmaxf(xp1 * 63.0f, 0.0f), 63.0f);

        int r0 = min((int)g0, 62);   // g >= 0, trunc == floor
        int c0 = min((int)g1, 62);
        const float fr = g0 - (float)r0;
        const float fc = g1 - (float)c0;

        const float* __restrict__ cell = sYp + r0 * GRD + c0;
        const float y00 = cell[0];
        const float y01 = cell[1];
        const float y10 = cell[GRD];
        const float y11 = cell[GRD + 1];

        const float top = fmaf(fc, y01 - y00, y00);
        const float bot = fmaf(fc, y11 - y10, y10);
        out[(size_t)b * NPAIRS + p] = fmaf(fr, bot - top, top);
    }
}

extern "C" void kernel_launch(void* const* d_in, const int* in_sizes, int n_in,
                              void* d_out, int out_size)
{
    const float* x     = (const float*)d_in[0];
    const float* pairW = (const float*)d_in[1];
    const float* Y     = (const float*)d_in[2];
    float* out         = (float*)d_out;

    const int batch = in_sizes[0] / DIM;   // 8192

    const int b_blocks = 4;
    const int b_tile = (batch + b_blocks - 1) / b_blocks;

    cudaFuncSetAttribute(pair_bilinear_kernel,
                         cudaFuncAttributeMaxDynamicSharedMemorySize, SMEM_BYTES);

    dim3 grid(NPAIRS / P_TILE, b_blocks);   // (256, 4)
    pair_bilinear_kernel<<<grid, THREADS, SMEM_BYTES>>>(x, pairW, Y, out, batch, b_tile);
}